// round 3
// baseline (speedup 1.0000x reference)
#include <cuda_runtime.h>
#include <cuda_bf16.h>
#include <stdint.h>

#define BB 2048
#define DD 20000
#define NA 3

struct Keys {
    uint32_t drop[NA][2], noise[NA][2], scl[NA][2], gmask[NA][2], gscl[NA][2];
    uint32_t sel[NA][2], pick[NA][2], coin[NA][2], ba[NA][2], bb[NA][2];
};

__device__ float g_lam[NA * BB];
__device__ int   g_jsel[NA * BB];
__device__ int   g_domix[NA * BB];
__device__ float g_scale[NA * BB];
__device__ int   g_ctxnew[NA * BB];
__device__ float g_gscale[NA * DD];

__host__ __device__ inline uint32_t rotl32(uint32_t v, int r) {
#ifdef __CUDA_ARCH__
    return __funnelshift_l(v, v, r);
#else
    return (v << r) | (v >> (32 - r));
#endif
}

// threefry2x32, 20 rounds, jax-compatible
__host__ __device__ inline void tf2x32(uint32_t k0, uint32_t k1,
                                       uint32_t x0, uint32_t x1,
                                       uint32_t& o0, uint32_t& o1) {
    uint32_t ks2 = k0 ^ k1 ^ 0x1BD11BDAu;
    x0 += k0; x1 += k1;
#define TF_R(r) { x0 += x1; x1 = rotl32(x1, r); x1 ^= x0; }
    TF_R(13) TF_R(15) TF_R(26) TF_R(6)
    x0 += k1;  x1 += ks2 + 1u;
    TF_R(17) TF_R(29) TF_R(16) TF_R(24)
    x0 += ks2; x1 += k0 + 2u;
    TF_R(13) TF_R(15) TF_R(26) TF_R(6)
    x0 += k0;  x1 += k1 + 3u;
    TF_R(17) TF_R(29) TF_R(16) TF_R(24)
    x0 += k1;  x1 += ks2 + 4u;
    TF_R(13) TF_R(15) TF_R(26) TF_R(6)
    x0 += ks2; x1 += k0 + 5u;
#undef TF_R
    o0 = x0; o1 = x1;
}

// partitionable random_bits(32): element i -> w0 ^ w1 of enc_key(0, i)
__device__ inline uint32_t rb32(uint32_t k0, uint32_t k1, uint32_t i) {
    uint32_t a, b;
    tf2x32(k0, k1, 0u, i, a, b);
    return a ^ b;
}

__device__ inline float u01(uint32_t bits) {
    return __uint_as_float((bits >> 9) | 0x3f800000u) - 1.0f;
}

// XLA ErfInv32 (Giles), rn-disciplined (no fma contraction)
__device__ inline float erfinv_f(float x) {
    float w = -log1pf(-__fmul_rn(x, x));
    float p;
    if (w < 5.0f) {
        w = __fsub_rn(w, 2.5f);
        p = 2.81022636e-08f;
        p = __fadd_rn(3.43273939e-07f,  __fmul_rn(p, w));
        p = __fadd_rn(-3.5233877e-06f,  __fmul_rn(p, w));
        p = __fadd_rn(-4.39150654e-06f, __fmul_rn(p, w));
        p = __fadd_rn(0.00021858087f,   __fmul_rn(p, w));
        p = __fadd_rn(-0.00125372503f,  __fmul_rn(p, w));
        p = __fadd_rn(-0.00417768164f,  __fmul_rn(p, w));
        p = __fadd_rn(0.246640727f,     __fmul_rn(p, w));
        p = __fadd_rn(1.50140941f,      __fmul_rn(p, w));
    } else {
        w = __fsub_rn(sqrtf(w), 3.0f);
        p = -0.000200214257f;
        p = __fadd_rn(0.000100950558f,  __fmul_rn(p, w));
        p = __fadd_rn(0.00134934322f,   __fmul_rn(p, w));
        p = __fadd_rn(-0.00367342844f,  __fmul_rn(p, w));
        p = __fadd_rn(0.00573950773f,   __fmul_rn(p, w));
        p = __fadd_rn(-0.0076224613f,   __fmul_rn(p, w));
        p = __fadd_rn(0.00943887047f,   __fmul_rn(p, w));
        p = __fadd_rn(1.00167406f,      __fmul_rn(p, w));
        p = __fadd_rn(2.83297682f,      __fmul_rn(p, w));
    }
    return __fmul_rn(p, x);
}

// jax.random.normal(f32) from raw bits
__device__ inline float normal_bits(uint32_t bits) {
    const float lo = __uint_as_float(0xBF7FFFFFu);       // nextafter(-1, 0)
    float u = __fadd_rn(__fmul_rn(u01(bits), 2.0f), lo); // (hi - lo) == 2.0f exactly
    u = fmaxf(lo, u);
    return __fmul_rn(__uint_as_float(0x3FB504F3u), erfinv_f(u)); // f32(sqrt(2))
}

// _gamma_one(key, alpha=0.4, log_space=True): Marsaglia-Tsang with log boost
__device__ float loggamma04(uint32_t k0, uint32_t k1) {
    uint32_t K0, K1, s0, s1;
    tf2x32(k0, k1, 0u, 0u, K0, K1);   // key    = split(key,2)[0]
    tf2x32(k0, k1, 0u, 1u, s0, s1);   // subkey = split(key,2)[1]
    float ub = u01(rb32(s0, s1, 0u));
    // log-space boost: log(1 - u) / alpha   (u in [0,1) => argument in (0,1])
    float log_boost = __fmul_rn(log1pf(-ub), 2.5f);
    const float d = __fsub_rn(__fadd_rn(0.4f, 1.0f), 0.33333334f);
    const float c = __fdiv_rn(0.33333334f, sqrtf(d));
    float X = 0.0f, V = 1.0f, U = 2.0f;
    for (int it = 0; it < 300; ++it) {
        bool c1 = (U >= __fsub_rn(1.0f, __fmul_rn(0.0331f, __fmul_rn(X, X))));
        if (!c1) break;
        float rhs = __fadd_rn(__fmul_rn(X, 0.5f),
                              __fmul_rn(d, __fadd_rn(__fsub_rn(1.0f, V), logf(V))));
        if (!(logf(U) >= rhs)) break;
        uint32_t nk0, nk1, xk0, xk1, uk0, uk1;
        tf2x32(K0, K1, 0u, 0u, nk0, nk1);   // key, x_key, U_key = split(key, 3)
        tf2x32(K0, K1, 0u, 1u, xk0, xk1);
        tf2x32(K0, K1, 0u, 2u, uk0, uk1);
        K0 = nk0; K1 = nk1;
        float x = 0.0f, v = -1.0f;
        uint32_t ck0 = xk0, ck1 = xk1;
        for (int g = 0; g < 300 && v <= 0.0f; ++g) {
            uint32_t m0, m1, t0, t1;
            tf2x32(ck0, ck1, 0u, 0u, m0, m1);   // key, subkey = split(key)
            tf2x32(ck0, ck1, 0u, 1u, t0, t1);
            x = normal_bits(rb32(t0, t1, 0u));
            v = __fadd_rn(1.0f, __fmul_rn(x, c));
            ck0 = m0; ck1 = m1;
        }
        X = __fmul_rn(x, x);
        V = __fmul_rn(__fmul_rn(v, v), v);
        U = u01(rb32(uk0, uk1, 0u));
    }
    return __fadd_rn(__fadd_rn(logf(d), logf(V)), log_boost);
}

// ---------------------------------------------------------------------------
// Kernel 1: per-(aug,row) setup — mixup selection, lambda, scale, new ctx
// ---------------------------------------------------------------------------
__global__ __launch_bounds__(256) void setup_rows(const int* __restrict__ ctx,
                                                  const int* __restrict__ y,
                                                  Keys K) {
    __shared__ int sy[BB];
    __shared__ int sc[BB];
    for (int t = threadIdx.x; t < BB; t += blockDim.x) { sy[t] = y[t]; sc[t] = ctx[t]; }
    __syncthreads();
    int i = blockIdx.x * blockDim.x + threadIdx.x;
    int a = blockIdx.y;
    if (i >= BB) return;
    int yi = sy[i], ci = sc[i];

    bool mix = u01(rb32(K.sel[a][0], K.sel[a][1], (uint32_t)i)) < 0.3f;

    int cnt = 0;
    for (int j = 0; j < BB; ++j)
        cnt += (sy[j] == yi) & (sc[j] != ci);

    float up = u01(rb32(K.pick[a][0], K.pick[a][1], (uint32_t)i));
    int kth = (int)floorf(__fmul_rn(up, (float)cnt));
    int hi = cnt - 1; if (hi < 0) hi = 0;
    if (kth > hi) kth = hi;

    int js = 0, cc = 0;
    for (int j = 0; j < BB; ++j) {
        if (sy[j] == yi && sc[j] != ci) {
            if (cc == kth) { js = j; break; }
            cc++;
        }
    }

    // lambda ~ Beta(0.4, 0.4): key_a, key_b = split(k_lam); per-sample = split(., B)[i]
    uint32_t ga0, ga1, gb0, gb1;
    tf2x32(K.ba[a][0], K.ba[a][1], 0u, (uint32_t)i, ga0, ga1);
    tf2x32(K.bb[a][0], K.bb[a][1], 0u, (uint32_t)i, gb0, gb1);
    float la = loggamma04(ga0, ga1);
    float lb = loggamma04(gb0, gb1);
    float lm = fmaxf(la, lb);
    float ea = expf(__fsub_rn(la, lm));
    float eb = expf(__fsub_rn(lb, lm));
    float lam = __fdiv_rn(ea, __fadd_rn(ea, eb));

    int dm = (mix && cnt > 0) ? 1 : 0;
    float us = u01(rb32(K.scl[a][0], K.scl[a][1], (uint32_t)i));
    float scale = __fadd_rn(__fmul_rn(us, 0.4f), 0.8f);
    bool coin = u01(rb32(K.coin[a][0], K.coin[a][1], (uint32_t)i)) < 0.5f;

    int r = a * BB + i;
    g_lam[r] = lam;
    g_jsel[r] = js;
    g_domix[r] = dm;
    g_scale[r] = scale;
    g_ctxnew[r] = (dm && !coin) ? sc[js] : ci;
}

// ---------------------------------------------------------------------------
// Kernel 2: per-(aug,gene) scale
// ---------------------------------------------------------------------------
__global__ __launch_bounds__(256) void setup_genes(Keys K) {
    int j = blockIdx.x * blockDim.x + threadIdx.x;
    int a = blockIdx.y;
    if (j >= DD) return;
    bool gm = u01(rb32(K.gmask[a][0], K.gmask[a][1], (uint32_t)j)) < 0.2f;
    float ug = u01(rb32(K.gscl[a][0], K.gscl[a][1], (uint32_t)j));
    g_gscale[a * DD + j] = gm ? __fadd_rn(__fmul_rn(ug, 0.4f), 0.8f) : 1.0f;
}

// ---------------------------------------------------------------------------
// Kernel 3: main elementwise augmentation — 2 threefry hashes + erfinv / elem
// ---------------------------------------------------------------------------
__global__ __launch_bounds__(256) void main_kernel(const float* __restrict__ x,
                                                   float* __restrict__ out, Keys K) {
    int a = blockIdx.z;
    int i = blockIdx.y;
    int j0 = (blockIdx.x * blockDim.x + threadIdx.x) * 4;
    if (j0 >= DD) return;

    int r = a * BB + i;
    float lam = g_lam[r];
    int   js  = g_jsel[r];
    int   dm  = g_domix[r];
    float sc  = g_scale[r];

    float4 xv = *(const float4*)(x + (size_t)i * DD + j0);
    float4 gs = *(const float4*)(&g_gscale[a * DD + j0]);
    if (dm) {
        float4 xj = *(const float4*)(x + (size_t)js * DD + j0);
        float oml = __fsub_rn(1.0f, lam);
        xv.x = __fadd_rn(__fmul_rn(lam, xv.x), __fmul_rn(oml, xj.x));
        xv.y = __fadd_rn(__fmul_rn(lam, xv.y), __fmul_rn(oml, xj.y));
        xv.z = __fadd_rn(__fmul_rn(lam, xv.z), __fmul_rn(oml, xj.z));
        xv.w = __fadd_rn(__fmul_rn(lam, xv.w), __fmul_rn(oml, xj.w));
    }

    uint32_t n = (uint32_t)i * (uint32_t)DD + (uint32_t)j0;
    uint32_t kd0 = K.drop[a][0],  kd1 = K.drop[a][1];
    uint32_t kn0 = K.noise[a][0], kn1 = K.noise[a][1];

    float v[4] = {xv.x, xv.y, xv.z, xv.w};
    float gsa[4] = {gs.x, gs.y, gs.z, gs.w};
    float res[4];
#pragma unroll
    for (int c = 0; c < 4; ++c) {
        uint32_t bd = rb32(kd0, kd1, n + (uint32_t)c);
        uint32_t bn = rb32(kn0, kn1, n + (uint32_t)c);
        float val = (u01(bd) > 0.2f) ? v[c] : 0.0f;   // aug * keep
        val = __fmul_rn(val, sc);                      // * scale
        val = __fmul_rn(val, gsa[c]);                  // * gscale
        float nz = normal_bits(bn);
        val = __fadd_rn(val, __fmul_rn(nz, 0.01f));    // + noise*0.01
        res[c] = fmaxf(val, 0.0f);
    }
    float4 o = make_float4(res[0], res[1], res[2], res[3]);
    *(float4*)(out + (size_t)r * DD + j0) = o;
}

// ---------------------------------------------------------------------------
// Kernel 4: concatenated tail outputs (ctx, y, cont_covs, cat_covs) as f32
// ---------------------------------------------------------------------------
__global__ __launch_bounds__(256) void tail_kernel(const int* __restrict__ ctx,
                                                   const int* __restrict__ y,
                                                   const float* __restrict__ cont,
                                                   const int* __restrict__ cat,
                                                   float* __restrict__ out) {
    int t = blockIdx.x * blockDim.x + threadIdx.x;
    const int s0 = NA * BB;            // ctx region
    const int s1 = NA * BB;            // y region
    const int s2 = NA * BB * 4;        // cont region
    const int s3 = NA * BB * 2;        // cat region
    if (t >= s0 + s1 + s2 + s3) return;
    size_t O = (size_t)NA * BB * DD;
    float val;
    if (t < s0) {
        val = (float)g_ctxnew[t];
    } else if (t < s0 + s1) {
        int u = t - s0;
        val = (float)y[u % BB];
    } else if (t < s0 + s1 + s2) {
        int u = t - s0 - s1;
        int i = (u / 4) % BB, c = u % 4;
        val = cont[i * 4 + c];
    } else {
        int u = t - s0 - s1 - s2;
        int i = (u / 2) % BB, c = u % 2;
        val = (float)cat[i * 2 + c];
    }
    out[O + t] = val;
}

// ---------------------------------------------------------------------------
extern "C" void kernel_launch(void* const* d_in, const int* in_sizes, int n_in,
                              void* d_out, int out_size) {
    const float* x    = (const float*)d_in[0];
    const int*   ctx  = (const int*)d_in[1];
    const int*   y    = (const int*)d_in[2];
    const float* cont = (const float*)d_in[3];
    const int*   cat  = (const int*)d_in[4];
    float* out = (float*)d_out;

    Keys K;
    for (int a = 0; a < NA; ++a) {
        uint32_t ka0, ka1;
        tf2x32(0u, 42u, 0u, (uint32_t)a, ka0, ka1);   // fold_in(key(42), a)
        uint32_t sub[6][2];
        for (int s = 0; s < 6; ++s)
            tf2x32(ka0, ka1, 0u, (uint32_t)s, sub[s][0], sub[s][1]);  // split(k, 6)
        // sub: 0=k_mix 1=k_drop 2=k_scale 3=k_gmask 4=k_gscale 5=k_noise
        K.drop[a][0]  = sub[1][0]; K.drop[a][1]  = sub[1][1];
        K.scl[a][0]   = sub[2][0]; K.scl[a][1]   = sub[2][1];
        K.gmask[a][0] = sub[3][0]; K.gmask[a][1] = sub[3][1];
        K.gscl[a][0]  = sub[4][0]; K.gscl[a][1]  = sub[4][1];
        K.noise[a][0] = sub[5][0]; K.noise[a][1] = sub[5][1];
        uint32_t m0 = sub[0][0], m1 = sub[0][1];
        uint32_t t0, t1;
        tf2x32(m0, m1, 0u, 0u, t0, t1); K.sel[a][0]  = t0; K.sel[a][1]  = t1;
        tf2x32(m0, m1, 0u, 1u, t0, t1); K.pick[a][0] = t0; K.pick[a][1] = t1;
        uint32_t lam0, lam1;
        tf2x32(m0, m1, 0u, 2u, lam0, lam1);
        tf2x32(m0, m1, 0u, 3u, t0, t1); K.coin[a][0] = t0; K.coin[a][1] = t1;
        tf2x32(lam0, lam1, 0u, 0u, t0, t1); K.ba[a][0] = t0; K.ba[a][1] = t1;  // key_a
        tf2x32(lam0, lam1, 0u, 1u, t0, t1); K.bb[a][0] = t0; K.bb[a][1] = t1;  // key_b
    }

    setup_rows<<<dim3((BB + 255) / 256, NA), 256>>>(ctx, y, K);
    setup_genes<<<dim3((DD + 255) / 256, NA), 256>>>(K);
    main_kernel<<<dim3((DD / 4 + 255) / 256, BB, NA), 256>>>(x, out, K);

    long long O = (long long)NA * BB * DD;
    int tail = NA * BB * 8;
    if ((long long)out_size >= O + tail)
        tail_kernel<<<(tail + 255) / 256, 256>>>(ctx, y, cont, cat, out);
}

// round 4
// speedup vs baseline: 1.1533x; 1.1533x over previous
#include <cuda_runtime.h>
#include <cuda_bf16.h>
#include <stdint.h>

#define BB 2048
#define DD 20000
#define NA 3

struct Keys {
    uint32_t drop[NA][2], noise[NA][2], scl[NA][2], gmask[NA][2], gscl[NA][2];
    uint32_t sel[NA][2], pick[NA][2], coin[NA][2], ba[NA][2], bb[NA][2];
};

__device__ float g_lam[NA * BB];
__device__ int   g_jsel[NA * BB];
__device__ int   g_domix[NA * BB];
__device__ float g_scale[NA * BB];
__device__ int   g_ctxnew[NA * BB];
__device__ float g_gscale[NA * DD];

__host__ __device__ inline uint32_t rotl32(uint32_t v, int r) {
#ifdef __CUDA_ARCH__
    return __funnelshift_l(v, v, r);
#else
    return (v << r) | (v >> (32 - r));
#endif
}

// threefry2x32, 20 rounds, jax-compatible
__host__ __device__ inline void tf2x32(uint32_t k0, uint32_t k1,
                                       uint32_t x0, uint32_t x1,
                                       uint32_t& o0, uint32_t& o1) {
    uint32_t ks2 = k0 ^ k1 ^ 0x1BD11BDAu;
    x0 += k0; x1 += k1;
#define TF_R(r) { x0 += x1; x1 = rotl32(x1, r); x1 ^= x0; }
    TF_R(13) TF_R(15) TF_R(26) TF_R(6)
    x0 += k1;  x1 += ks2 + 1u;
    TF_R(17) TF_R(29) TF_R(16) TF_R(24)
    x0 += ks2; x1 += k0 + 2u;
    TF_R(13) TF_R(15) TF_R(26) TF_R(6)
    x0 += k0;  x1 += k1 + 3u;
    TF_R(17) TF_R(29) TF_R(16) TF_R(24)
    x0 += k1;  x1 += ks2 + 4u;
    TF_R(13) TF_R(15) TF_R(26) TF_R(6)
    x0 += ks2; x1 += k0 + 5u;
#undef TF_R
    o0 = x0; o1 = x1;
}

// partitionable random_bits(32): element i -> w0 ^ w1 of enc_key(0, i)
__device__ inline uint32_t rb32(uint32_t k0, uint32_t k1, uint32_t i) {
    uint32_t a, b;
    tf2x32(k0, k1, 0u, i, a, b);
    return a ^ b;
}

__device__ inline float u01(uint32_t bits) {
    return __uint_as_float((bits >> 9) | 0x3f800000u) - 1.0f;
}

// ---------------- exact path (used by beta sampling; branch decisions) -----
__device__ inline float erfinv_f(float x) {
    float w = -log1pf(-__fmul_rn(x, x));
    float p;
    if (w < 5.0f) {
        w = __fsub_rn(w, 2.5f);
        p = 2.81022636e-08f;
        p = __fadd_rn(3.43273939e-07f,  __fmul_rn(p, w));
        p = __fadd_rn(-3.5233877e-06f,  __fmul_rn(p, w));
        p = __fadd_rn(-4.39150654e-06f, __fmul_rn(p, w));
        p = __fadd_rn(0.00021858087f,   __fmul_rn(p, w));
        p = __fadd_rn(-0.00125372503f,  __fmul_rn(p, w));
        p = __fadd_rn(-0.00417768164f,  __fmul_rn(p, w));
        p = __fadd_rn(0.246640727f,     __fmul_rn(p, w));
        p = __fadd_rn(1.50140941f,      __fmul_rn(p, w));
    } else {
        w = __fsub_rn(sqrtf(w), 3.0f);
        p = -0.000200214257f;
        p = __fadd_rn(0.000100950558f,  __fmul_rn(p, w));
        p = __fadd_rn(0.00134934322f,   __fmul_rn(p, w));
        p = __fadd_rn(-0.00367342844f,  __fmul_rn(p, w));
        p = __fadd_rn(0.00573950773f,   __fmul_rn(p, w));
        p = __fadd_rn(-0.0076224613f,   __fmul_rn(p, w));
        p = __fadd_rn(0.00943887047f,   __fmul_rn(p, w));
        p = __fadd_rn(1.00167406f,      __fmul_rn(p, w));
        p = __fadd_rn(2.83297682f,      __fmul_rn(p, w));
    }
    return __fmul_rn(p, x);
}

__device__ inline float normal_bits(uint32_t bits) {
    const float lo = __uint_as_float(0xBF7FFFFFu);
    float u = __fadd_rn(__fmul_rn(u01(bits), 2.0f), lo);
    u = fmaxf(lo, u);
    return __fmul_rn(__uint_as_float(0x3FB504F3u), erfinv_f(u));
}

// ---------------- fast path (noise only; ~1e-6 accuracy, budget 6e-2) -----
__device__ inline float normal_fast(uint32_t bits) {
    const float lo = __uint_as_float(0xBF7FFFFFu);
    float x = fmaf(u01(bits), 2.0f, lo);
    x = fmaxf(lo, x);
    float w = -__logf(fmaf(-x, x, 1.0f));     // MUFU.LG2 path
    float p;
    if (w < 5.0f) {
        w = w - 2.5f;
        p =      2.81022636e-08f;
        p = fmaf(p, w, 3.43273939e-07f);
        p = fmaf(p, w, -3.5233877e-06f);
        p = fmaf(p, w, -4.39150654e-06f);
        p = fmaf(p, w, 0.00021858087f);
        p = fmaf(p, w, -0.00125372503f);
        p = fmaf(p, w, -0.00417768164f);
        p = fmaf(p, w, 0.246640727f);
        p = fmaf(p, w, 1.50140941f);
    } else {
        w = sqrtf(w) - 3.0f;
        p =      -0.000200214257f;
        p = fmaf(p, w, 0.000100950558f);
        p = fmaf(p, w, 0.00134934322f);
        p = fmaf(p, w, -0.00367342844f);
        p = fmaf(p, w, 0.00573950773f);
        p = fmaf(p, w, -0.0076224613f);
        p = fmaf(p, w, 0.00943887047f);
        p = fmaf(p, w, 1.00167406f);
        p = fmaf(p, w, 2.83297682f);
    }
    return 1.41421356f * (p * x);
}

// _gamma_one(key, alpha=0.4, log_space=True): Marsaglia-Tsang with log boost
__device__ float loggamma04(uint32_t k0, uint32_t k1) {
    uint32_t K0, K1, s0, s1;
    tf2x32(k0, k1, 0u, 0u, K0, K1);
    tf2x32(k0, k1, 0u, 1u, s0, s1);
    float ub = u01(rb32(s0, s1, 0u));
    float log_boost = __fmul_rn(log1pf(-ub), 2.5f);
    const float d = __fsub_rn(__fadd_rn(0.4f, 1.0f), 0.33333334f);
    const float c = __fdiv_rn(0.33333334f, sqrtf(d));
    float X = 0.0f, V = 1.0f, U = 2.0f;
    for (int it = 0; it < 300; ++it) {
        bool c1 = (U >= __fsub_rn(1.0f, __fmul_rn(0.0331f, __fmul_rn(X, X))));
        if (!c1) break;
        float rhs = __fadd_rn(__fmul_rn(X, 0.5f),
                              __fmul_rn(d, __fadd_rn(__fsub_rn(1.0f, V), logf(V))));
        if (!(logf(U) >= rhs)) break;
        uint32_t nk0, nk1, xk0, xk1, uk0, uk1;
        tf2x32(K0, K1, 0u, 0u, nk0, nk1);
        tf2x32(K0, K1, 0u, 1u, xk0, xk1);
        tf2x32(K0, K1, 0u, 2u, uk0, uk1);
        K0 = nk0; K1 = nk1;
        float x = 0.0f, v = -1.0f;
        uint32_t ck0 = xk0, ck1 = xk1;
        for (int g = 0; g < 300 && v <= 0.0f; ++g) {
            uint32_t m0, m1, t0, t1;
            tf2x32(ck0, ck1, 0u, 0u, m0, m1);
            tf2x32(ck0, ck1, 0u, 1u, t0, t1);
            x = normal_bits(rb32(t0, t1, 0u));
            v = __fadd_rn(1.0f, __fmul_rn(x, c));
            ck0 = m0; ck1 = m1;
        }
        X = __fmul_rn(x, x);
        V = __fmul_rn(__fmul_rn(v, v), v);
        U = u01(rb32(uk0, uk1, 0u));
    }
    return __fadd_rn(__fadd_rn(logf(d), logf(V)), log_boost);
}

// ---------------------------------------------------------------------------
// Kernel 1: per-(aug,row) setup
// ---------------------------------------------------------------------------
__global__ __launch_bounds__(256) void setup_rows(const int* __restrict__ ctx,
                                                  const int* __restrict__ y,
                                                  Keys K) {
    __shared__ int sy[BB];
    __shared__ int sc[BB];
    for (int t = threadIdx.x; t < BB; t += blockDim.x) { sy[t] = y[t]; sc[t] = ctx[t]; }
    __syncthreads();
    int i = blockIdx.x * blockDim.x + threadIdx.x;
    int a = blockIdx.y;
    if (i >= BB) return;
    int yi = sy[i], ci = sc[i];

    bool mix = u01(rb32(K.sel[a][0], K.sel[a][1], (uint32_t)i)) < 0.3f;

    int cnt = 0;
    for (int j = 0; j < BB; ++j)
        cnt += (sy[j] == yi) & (sc[j] != ci);

    float up = u01(rb32(K.pick[a][0], K.pick[a][1], (uint32_t)i));
    int kth = (int)floorf(__fmul_rn(up, (float)cnt));
    int hi = cnt - 1; if (hi < 0) hi = 0;
    if (kth > hi) kth = hi;

    int js = 0, cc = 0;
    for (int j = 0; j < BB; ++j) {
        if (sy[j] == yi && sc[j] != ci) {
            if (cc == kth) { js = j; break; }
            cc++;
        }
    }

    uint32_t ga0, ga1, gb0, gb1;
    tf2x32(K.ba[a][0], K.ba[a][1], 0u, (uint32_t)i, ga0, ga1);
    tf2x32(K.bb[a][0], K.bb[a][1], 0u, (uint32_t)i, gb0, gb1);
    float la = loggamma04(ga0, ga1);
    float lb = loggamma04(gb0, gb1);
    float lm = fmaxf(la, lb);
    float ea = expf(__fsub_rn(la, lm));
    float eb = expf(__fsub_rn(lb, lm));
    float lam = __fdiv_rn(ea, __fadd_rn(ea, eb));

    int dm = (mix && cnt > 0) ? 1 : 0;
    float us = u01(rb32(K.scl[a][0], K.scl[a][1], (uint32_t)i));
    float scale = __fadd_rn(__fmul_rn(us, 0.4f), 0.8f);
    bool coin = u01(rb32(K.coin[a][0], K.coin[a][1], (uint32_t)i)) < 0.5f;

    int r = a * BB + i;
    g_lam[r] = lam;
    g_jsel[r] = js;
    g_domix[r] = dm;
    g_scale[r] = scale;
    g_ctxnew[r] = (dm && !coin) ? sc[js] : ci;
}

// ---------------------------------------------------------------------------
// Kernel 2: per-(aug,gene) scale
// ---------------------------------------------------------------------------
__global__ __launch_bounds__(256) void setup_genes(Keys K) {
    int j = blockIdx.x * blockDim.x + threadIdx.x;
    int a = blockIdx.y;
    if (j >= DD) return;
    bool gm = u01(rb32(K.gmask[a][0], K.gmask[a][1], (uint32_t)j)) < 0.2f;
    float ug = u01(rb32(K.gscl[a][0], K.gscl[a][1], (uint32_t)j));
    g_gscale[a * DD + j] = gm ? __fadd_rn(__fmul_rn(ug, 0.4f), 0.8f) : 1.0f;
}

// ---------------------------------------------------------------------------
// Kernel 3: main elementwise augmentation
//   keep mask:  u01(bd) > 0.2  <=>  bd >= 858993664u   (exact integer form)
//   value path uses fmaf/fast-log: error ~1e-6 abs vs 6e-2 budget
// ---------------------------------------------------------------------------
__global__ __launch_bounds__(256) void main_kernel(const float* __restrict__ x,
                                                   float* __restrict__ out, Keys K) {
    int a = blockIdx.z;
    int i = blockIdx.y;
    int j0 = (blockIdx.x * blockDim.x + threadIdx.x) * 4;
    if (j0 >= DD) return;

    int r = a * BB + i;
    float lam = g_lam[r];
    int   js  = g_jsel[r];
    int   dm  = g_domix[r];
    float sc  = g_scale[r];

    float4 xv = *(const float4*)(x + (size_t)i * DD + j0);
    float4 gs = *(const float4*)(&g_gscale[a * DD + j0]);
    if (dm) {
        float4 xj = *(const float4*)(x + (size_t)js * DD + j0);
        // lam*x + (1-lam)*xj  ==  fmaf(lam, x - xj, xj)  (~1e-7 rel delta, in budget)
        xv.x = fmaf(lam, xv.x - xj.x, xj.x);
        xv.y = fmaf(lam, xv.y - xj.y, xj.y);
        xv.z = fmaf(lam, xv.z - xj.z, xj.z);
        xv.w = fmaf(lam, xv.w - xj.w, xj.w);
    }

    uint32_t n = (uint32_t)i * (uint32_t)DD + (uint32_t)j0;
    uint32_t kd0 = K.drop[a][0],  kd1 = K.drop[a][1];
    uint32_t kn0 = K.noise[a][0], kn1 = K.noise[a][1];

    float v[4]   = {xv.x, xv.y, xv.z, xv.w};
    float gsa[4] = {gs.x, gs.y, gs.z, gs.w};
    float res[4];
#pragma unroll
    for (int c = 0; c < 4; ++c) {
        uint32_t bd = rb32(kd0, kd1, n + (uint32_t)c);
        uint32_t bn = rb32(kn0, kn1, n + (uint32_t)c);
        float sg  = sc * gsa[c];
        float val = (bd >= 858993664u) ? v[c] * sg : 0.0f;
        float nz  = normal_fast(bn);
        res[c] = fmaxf(fmaf(nz, 0.01f, val), 0.0f);
    }
    float4 o = make_float4(res[0], res[1], res[2], res[3]);
    __stcs((float4*)(out + (size_t)r * DD + j0), o);
}

// ---------------------------------------------------------------------------
// Kernel 4: concatenated tail outputs
// ---------------------------------------------------------------------------
__global__ __launch_bounds__(256) void tail_kernel(const int* __restrict__ ctx,
                                                   const int* __restrict__ y,
                                                   const float* __restrict__ cont,
                                                   const int* __restrict__ cat,
                                                   float* __restrict__ out) {
    int t = blockIdx.x * blockDim.x + threadIdx.x;
    const int s0 = NA * BB;
    const int s1 = NA * BB;
    const int s2 = NA * BB * 4;
    const int s3 = NA * BB * 2;
    if (t >= s0 + s1 + s2 + s3) return;
    size_t O = (size_t)NA * BB * DD;
    float val;
    if (t < s0) {
        val = (float)g_ctxnew[t];
    } else if (t < s0 + s1) {
        int u = t - s0;
        val = (float)y[u % BB];
    } else if (t < s0 + s1 + s2) {
        int u = t - s0 - s1;
        int i = (u / 4) % BB, c = u % 4;
        val = cont[i * 4 + c];
    } else {
        int u = t - s0 - s1 - s2;
        int i = (u / 2) % BB, c = u % 2;
        val = (float)cat[i * 2 + c];
    }
    out[O + t] = val;
}

// ---------------------------------------------------------------------------
extern "C" void kernel_launch(void* const* d_in, const int* in_sizes, int n_in,
                              void* d_out, int out_size) {
    const float* x    = (const float*)d_in[0];
    const int*   ctx  = (const int*)d_in[1];
    const int*   y    = (const int*)d_in[2];
    const float* cont = (const float*)d_in[3];
    const int*   cat  = (const int*)d_in[4];
    float* out = (float*)d_out;

    Keys K;
    for (int a = 0; a < NA; ++a) {
        uint32_t ka0, ka1;
        tf2x32(0u, 42u, 0u, (uint32_t)a, ka0, ka1);   // fold_in(key(42), a)
        uint32_t sub[6][2];
        for (int s = 0; s < 6; ++s)
            tf2x32(ka0, ka1, 0u, (uint32_t)s, sub[s][0], sub[s][1]);  // split(k, 6)
        K.drop[a][0]  = sub[1][0]; K.drop[a][1]  = sub[1][1];
        K.scl[a][0]   = sub[2][0]; K.scl[a][1]   = sub[2][1];
        K.gmask[a][0] = sub[3][0]; K.gmask[a][1] = sub[3][1];
        K.gscl[a][0]  = sub[4][0]; K.gscl[a][1]  = sub[4][1];
        K.noise[a][0] = sub[5][0]; K.noise[a][1] = sub[5][1];
        uint32_t m0 = sub[0][0], m1 = sub[0][1];
        uint32_t t0, t1;
        tf2x32(m0, m1, 0u, 0u, t0, t1); K.sel[a][0]  = t0; K.sel[a][1]  = t1;
        tf2x32(m0, m1, 0u, 1u, t0, t1); K.pick[a][0] = t0; K.pick[a][1] = t1;
        uint32_t lam0, lam1;
        tf2x32(m0, m1, 0u, 2u, lam0, lam1);
        tf2x32(m0, m1, 0u, 3u, t0, t1); K.coin[a][0] = t0; K.coin[a][1] = t1;
        tf2x32(lam0, lam1, 0u, 0u, t0, t1); K.ba[a][0] = t0; K.ba[a][1] = t1;
        tf2x32(lam0, lam1, 0u, 1u, t0, t1); K.bb[a][0] = t0; K.bb[a][1] = t1;
    }

    setup_rows<<<dim3((BB + 255) / 256, NA), 256>>>(ctx, y, K);
    setup_genes<<<dim3((DD + 255) / 256, NA), 256>>>(K);
    main_kernel<<<dim3((DD / 4 + 255) / 256, BB, NA), 256>>>(x, out, K);

    long long O = (long long)NA * BB * DD;
    int tail = NA * BB * 8;
    if ((long long)out_size >= O + tail)
        tail_kernel<<<(tail + 255) / 256, 256>>>(ctx, y, cont, cat, out);
}

// round 5
// speedup vs baseline: 1.2138x; 1.0525x over previous
#include <cuda_runtime.h>
#include <cuda_bf16.h>
#include <stdint.h>

#define BB 2048
#define DD 20000
#define NA 3

struct Keys {
    uint32_t drop[NA][2], noise[NA][2], scl[NA][2], gmask[NA][2], gscl[NA][2];
    uint32_t sel[NA][2], pick[NA][2], coin[NA][2], ba[NA][2], bb[NA][2];
};

__device__ float g_lam[NA * BB];
__device__ int   g_jsel[NA * BB];
__device__ int   g_domix[NA * BB];
__device__ float g_scale[NA * BB];
__device__ int   g_ctxnew[NA * BB];
__device__ float g_gscale[NA * DD];

__host__ __device__ inline uint32_t rotl32(uint32_t v, int r) {
#ifdef __CUDA_ARCH__
    return __funnelshift_l(v, v, r);
#else
    return (v << r) | (v >> (32 - r));
#endif
}

// threefry2x32, 20 rounds, jax-compatible
__host__ __device__ inline void tf2x32(uint32_t k0, uint32_t k1,
                                       uint32_t x0, uint32_t x1,
                                       uint32_t& o0, uint32_t& o1) {
    uint32_t ks2 = k0 ^ k1 ^ 0x1BD11BDAu;
    x0 += k0; x1 += k1;
#define TF_R(r) { x0 += x1; x1 = rotl32(x1, r); x1 ^= x0; }
    TF_R(13) TF_R(15) TF_R(26) TF_R(6)
    x0 += k1;  x1 += ks2 + 1u;
    TF_R(17) TF_R(29) TF_R(16) TF_R(24)
    x0 += ks2; x1 += k0 + 2u;
    TF_R(13) TF_R(15) TF_R(26) TF_R(6)
    x0 += k0;  x1 += k1 + 3u;
    TF_R(17) TF_R(29) TF_R(16) TF_R(24)
    x0 += k1;  x1 += ks2 + 4u;
    TF_R(13) TF_R(15) TF_R(26) TF_R(6)
    x0 += ks2; x1 += k0 + 5u;
#undef TF_R
    o0 = x0; o1 = x1;
}

// partitionable random_bits(32): element i -> w0 ^ w1 of enc_key(0, i)
__device__ inline uint32_t rb32(uint32_t k0, uint32_t k1, uint32_t i) {
    uint32_t a, b;
    tf2x32(k0, k1, 0u, i, a, b);
    return a ^ b;
}

__device__ inline float u01(uint32_t bits) {
    return __uint_as_float((bits >> 9) | 0x3f800000u) - 1.0f;
}

// ---------------- exact path (beta sampling; branch decisions) -------------
__device__ inline float erfinv_f(float x) {
    float w = -log1pf(-__fmul_rn(x, x));
    float p;
    if (w < 5.0f) {
        w = __fsub_rn(w, 2.5f);
        p = 2.81022636e-08f;
        p = __fadd_rn(3.43273939e-07f,  __fmul_rn(p, w));
        p = __fadd_rn(-3.5233877e-06f,  __fmul_rn(p, w));
        p = __fadd_rn(-4.39150654e-06f, __fmul_rn(p, w));
        p = __fadd_rn(0.00021858087f,   __fmul_rn(p, w));
        p = __fadd_rn(-0.00125372503f,  __fmul_rn(p, w));
        p = __fadd_rn(-0.00417768164f,  __fmul_rn(p, w));
        p = __fadd_rn(0.246640727f,     __fmul_rn(p, w));
        p = __fadd_rn(1.50140941f,      __fmul_rn(p, w));
    } else {
        w = __fsub_rn(sqrtf(w), 3.0f);
        p = -0.000200214257f;
        p = __fadd_rn(0.000100950558f,  __fmul_rn(p, w));
        p = __fadd_rn(0.00134934322f,   __fmul_rn(p, w));
        p = __fadd_rn(-0.00367342844f,  __fmul_rn(p, w));
        p = __fadd_rn(0.00573950773f,   __fmul_rn(p, w));
        p = __fadd_rn(-0.0076224613f,   __fmul_rn(p, w));
        p = __fadd_rn(0.00943887047f,   __fmul_rn(p, w));
        p = __fadd_rn(1.00167406f,      __fmul_rn(p, w));
        p = __fadd_rn(2.83297682f,      __fmul_rn(p, w));
    }
    return __fmul_rn(p, x);
}

__device__ inline float normal_bits(uint32_t bits) {
    const float lo = __uint_as_float(0xBF7FFFFFu);
    float u = __fadd_rn(__fmul_rn(u01(bits), 2.0f), lo);
    u = fmaxf(lo, u);
    return __fmul_rn(__uint_as_float(0x3FB504F3u), erfinv_f(u));
}

// ---------------- cheap noise path: err <= ~2e-3 on N, budget ~6e-2 --------
// sqrt(2) folded into coefficients; central poly truncated to 5 terms,
// tail to 4.  x shifted by -1.8e-7 so 1-x^2 stays positive at the corner.
__device__ inline float normal_cheap(uint32_t bits) {
    float uf = __uint_as_float((bits >> 9) | 0x3f800000u);   // [1,2)
    float x  = fmaf(uf, 2.0f, -2.99999976f);                  // ~2u-1 in (-1,1)
    float w  = -__logf(fmaf(-x, x, 1.0f));                    // MUFU.LG2
    float p;
    if (w < 5.0f) {
        w = w - 2.5f;
        p = fmaf(0.00030912038f, w, -0.0017730364f);
        p = fmaf(p, w, -0.0059081367f);
        p = fmaf(p, w, 0.34880113f);
        p = fmaf(p, w, 2.1233314f);
    } else {
        w = __fsqrt_rn(w) - 3.0f;
        p = fmaf(-0.010779899f, w, 0.013348666f);
        p = fmaf(p, w, 1.4165807f);
        p = fmaf(p, w, 4.0064883f);
    }
    return p * x;   // already scaled by sqrt(2)
}

// _gamma_one(key, alpha=0.4, log_space=True): Marsaglia-Tsang with log boost
__device__ float loggamma04(uint32_t k0, uint32_t k1) {
    uint32_t K0, K1, s0, s1;
    tf2x32(k0, k1, 0u, 0u, K0, K1);
    tf2x32(k0, k1, 0u, 1u, s0, s1);
    float ub = u01(rb32(s0, s1, 0u));
    float log_boost = __fmul_rn(log1pf(-ub), 2.5f);
    const float d = __fsub_rn(__fadd_rn(0.4f, 1.0f), 0.33333334f);
    const float c = __fdiv_rn(0.33333334f, sqrtf(d));
    float X = 0.0f, V = 1.0f, U = 2.0f;
    for (int it = 0; it < 300; ++it) {
        bool c1 = (U >= __fsub_rn(1.0f, __fmul_rn(0.0331f, __fmul_rn(X, X))));
        if (!c1) break;
        float rhs = __fadd_rn(__fmul_rn(X, 0.5f),
                              __fmul_rn(d, __fadd_rn(__fsub_rn(1.0f, V), logf(V))));
        if (!(logf(U) >= rhs)) break;
        uint32_t nk0, nk1, xk0, xk1, uk0, uk1;
        tf2x32(K0, K1, 0u, 0u, nk0, nk1);
        tf2x32(K0, K1, 0u, 1u, xk0, xk1);
        tf2x32(K0, K1, 0u, 2u, uk0, uk1);
        K0 = nk0; K1 = nk1;
        float x = 0.0f, v = -1.0f;
        uint32_t ck0 = xk0, ck1 = xk1;
        for (int g = 0; g < 300 && v <= 0.0f; ++g) {
            uint32_t m0, m1, t0, t1;
            tf2x32(ck0, ck1, 0u, 0u, m0, m1);
            tf2x32(ck0, ck1, 0u, 1u, t0, t1);
            x = normal_bits(rb32(t0, t1, 0u));
            v = __fadd_rn(1.0f, __fmul_rn(x, c));
            ck0 = m0; ck1 = m1;
        }
        X = __fmul_rn(x, x);
        V = __fmul_rn(__fmul_rn(v, v), v);
        U = u01(rb32(uk0, uk1, 0u));
    }
    return __fadd_rn(__fadd_rn(logf(d), logf(V)), log_boost);
}

// ---------------------------------------------------------------------------
// Kernel 1: per-(aug,row) setup
// ---------------------------------------------------------------------------
__global__ __launch_bounds__(256) void setup_rows(const int* __restrict__ ctx,
                                                  const int* __restrict__ y,
                                                  Keys K) {
    __shared__ int sy[BB];
    __shared__ int sc[BB];
    for (int t = threadIdx.x; t < BB; t += blockDim.x) { sy[t] = y[t]; sc[t] = ctx[t]; }
    __syncthreads();
    int i = blockIdx.x * blockDim.x + threadIdx.x;
    int a = blockIdx.y;
    if (i >= BB) return;
    int yi = sy[i], ci = sc[i];

    bool mix = u01(rb32(K.sel[a][0], K.sel[a][1], (uint32_t)i)) < 0.3f;

    int cnt = 0;
    for (int j = 0; j < BB; ++j)
        cnt += (sy[j] == yi) & (sc[j] != ci);

    float up = u01(rb32(K.pick[a][0], K.pick[a][1], (uint32_t)i));
    int kth = (int)floorf(__fmul_rn(up, (float)cnt));
    int hi = cnt - 1; if (hi < 0) hi = 0;
    if (kth > hi) kth = hi;

    int js = 0, cc = 0;
    for (int j = 0; j < BB; ++j) {
        if (sy[j] == yi && sc[j] != ci) {
            if (cc == kth) { js = j; break; }
            cc++;
        }
    }

    uint32_t ga0, ga1, gb0, gb1;
    tf2x32(K.ba[a][0], K.ba[a][1], 0u, (uint32_t)i, ga0, ga1);
    tf2x32(K.bb[a][0], K.bb[a][1], 0u, (uint32_t)i, gb0, gb1);
    float la = loggamma04(ga0, ga1);
    float lb = loggamma04(gb0, gb1);
    float lm = fmaxf(la, lb);
    float ea = expf(__fsub_rn(la, lm));
    float eb = expf(__fsub_rn(lb, lm));
    float lam = __fdiv_rn(ea, __fadd_rn(ea, eb));

    int dm = (mix && cnt > 0) ? 1 : 0;
    float us = u01(rb32(K.scl[a][0], K.scl[a][1], (uint32_t)i));
    float scale = __fadd_rn(__fmul_rn(us, 0.4f), 0.8f);
    bool coin = u01(rb32(K.coin[a][0], K.coin[a][1], (uint32_t)i)) < 0.5f;

    int r = a * BB + i;
    g_lam[r] = lam;
    g_jsel[r] = js;
    g_domix[r] = dm;
    g_scale[r] = scale;
    g_ctxnew[r] = (dm && !coin) ? sc[js] : ci;
}

// ---------------------------------------------------------------------------
// Kernel 2: per-(aug,gene) scale
// ---------------------------------------------------------------------------
__global__ __launch_bounds__(256) void setup_genes(Keys K) {
    int j = blockIdx.x * blockDim.x + threadIdx.x;
    int a = blockIdx.y;
    if (j >= DD) return;
    bool gm = u01(rb32(K.gmask[a][0], K.gmask[a][1], (uint32_t)j)) < 0.2f;
    float ug = u01(rb32(K.gscl[a][0], K.gscl[a][1], (uint32_t)j));
    g_gscale[a * DD + j] = gm ? __fadd_rn(__fmul_rn(ug, 0.4f), 0.8f) : 1.0f;
}

// ---------------------------------------------------------------------------
// Kernel 3: main elementwise augmentation, 8 elems/thread
//   keep mask:  u01(bd) > 0.2  <=>  bd >= 858993664u   (exact integer form)
// ---------------------------------------------------------------------------
__global__ __launch_bounds__(256) void main_kernel(const float* __restrict__ x,
                                                   float* __restrict__ out, Keys K) {
    int a = blockIdx.z;
    int i = blockIdx.y;
    int j0 = (blockIdx.x * blockDim.x + threadIdx.x) * 8;
    if (j0 >= DD) return;               // DD % 8 == 0, clean guard

    int r = a * BB + i;
    float lam = g_lam[r];
    int   js  = g_jsel[r];
    int   dm  = g_domix[r];
    float sc  = g_scale[r];

    const float* xr = x + (size_t)i * DD + j0;
    float4 xv0 = *(const float4*)(xr);
    float4 xv1 = *(const float4*)(xr + 4);
    float4 gs0 = *(const float4*)(&g_gscale[a * DD + j0]);
    float4 gs1 = *(const float4*)(&g_gscale[a * DD + j0 + 4]);

    float v[8]   = {xv0.x, xv0.y, xv0.z, xv0.w, xv1.x, xv1.y, xv1.z, xv1.w};
    float gsa[8] = {gs0.x, gs0.y, gs0.z, gs0.w, gs1.x, gs1.y, gs1.z, gs1.w};

    if (dm) {
        const float* xjr = x + (size_t)js * DD + j0;
        float4 xj0 = *(const float4*)(xjr);
        float4 xj1 = *(const float4*)(xjr + 4);
        float xj[8] = {xj0.x, xj0.y, xj0.z, xj0.w, xj1.x, xj1.y, xj1.z, xj1.w};
#pragma unroll
        for (int c = 0; c < 8; ++c)
            v[c] = fmaf(lam, v[c] - xj[c], xj[c]);   // lam*x + (1-lam)*xj
    }

    uint32_t n = (uint32_t)i * (uint32_t)DD + (uint32_t)j0;
    uint32_t kd0 = K.drop[a][0],  kd1 = K.drop[a][1];
    uint32_t kn0 = K.noise[a][0], kn1 = K.noise[a][1];

    float res[8];
#pragma unroll
    for (int c = 0; c < 8; ++c) {
        uint32_t bd = rb32(kd0, kd1, n + (uint32_t)c);
        uint32_t bn = rb32(kn0, kn1, n + (uint32_t)c);
        float val = (bd >= 858993664u) ? v[c] * (sc * gsa[c]) : 0.0f;
        float nz  = normal_cheap(bn);
        res[c] = fmaxf(fmaf(nz, 0.01f, val), 0.0f);
    }

    float* orow = out + (size_t)r * DD + j0;
    __stcs((float4*)(orow),     make_float4(res[0], res[1], res[2], res[3]));
    __stcs((float4*)(orow + 4), make_float4(res[4], res[5], res[6], res[7]));
}

// ---------------------------------------------------------------------------
// Kernel 4: concatenated tail outputs
// ---------------------------------------------------------------------------
__global__ __launch_bounds__(256) void tail_kernel(const int* __restrict__ ctx,
                                                   const int* __restrict__ y,
                                                   const float* __restrict__ cont,
                                                   const int* __restrict__ cat,
                                                   float* __restrict__ out) {
    int t = blockIdx.x * blockDim.x + threadIdx.x;
    const int s0 = NA * BB;
    const int s1 = NA * BB;
    const int s2 = NA * BB * 4;
    const int s3 = NA * BB * 2;
    if (t >= s0 + s1 + s2 + s3) return;
    size_t O = (size_t)NA * BB * DD;
    float val;
    if (t < s0) {
        val = (float)g_ctxnew[t];
    } else if (t < s0 + s1) {
        int u = t - s0;
        val = (float)y[u % BB];
    } else if (t < s0 + s1 + s2) {
        int u = t - s0 - s1;
        int i = (u / 4) % BB, c = u % 4;
        val = cont[i * 4 + c];
    } else {
        int u = t - s0 - s1 - s2;
        int i = (u / 2) % BB, c = u % 2;
        val = (float)cat[i * 2 + c];
    }
    out[O + t] = val;
}

// ---------------------------------------------------------------------------
extern "C" void kernel_launch(void* const* d_in, const int* in_sizes, int n_in,
                              void* d_out, int out_size) {
    const float* x    = (const float*)d_in[0];
    const int*   ctx  = (const int*)d_in[1];
    const int*   y    = (const int*)d_in[2];
    const float* cont = (const float*)d_in[3];
    const int*   cat  = (const int*)d_in[4];
    float* out = (float*)d_out;

    Keys K;
    for (int a = 0; a < NA; ++a) {
        uint32_t ka0, ka1;
        tf2x32(0u, 42u, 0u, (uint32_t)a, ka0, ka1);   // fold_in(key(42), a)
        uint32_t sub[6][2];
        for (int s = 0; s < 6; ++s)
            tf2x32(ka0, ka1, 0u, (uint32_t)s, sub[s][0], sub[s][1]);  // split(k, 6)
        K.drop[a][0]  = sub[1][0]; K.drop[a][1]  = sub[1][1];
        K.scl[a][0]   = sub[2][0]; K.scl[a][1]   = sub[2][1];
        K.gmask[a][0] = sub[3][0]; K.gmask[a][1] = sub[3][1];
        K.gscl[a][0]  = sub[4][0]; K.gscl[a][1]  = sub[4][1];
        K.noise[a][0] = sub[5][0]; K.noise[a][1] = sub[5][1];
        uint32_t m0 = sub[0][0], m1 = sub[0][1];
        uint32_t t0, t1;
        tf2x32(m0, m1, 0u, 0u, t0, t1); K.sel[a][0]  = t0; K.sel[a][1]  = t1;
        tf2x32(m0, m1, 0u, 1u, t0, t1); K.pick[a][0] = t0; K.pick[a][1] = t1;
        uint32_t lam0, lam1;
        tf2x32(m0, m1, 0u, 2u, lam0, lam1);
        tf2x32(m0, m1, 0u, 3u, t0, t1); K.coin[a][0] = t0; K.coin[a][1] = t1;
        tf2x32(lam0, lam1, 0u, 0u, t0, t1); K.ba[a][0] = t0; K.ba[a][1] = t1;
        tf2x32(lam0, lam1, 0u, 1u, t0, t1); K.bb[a][0] = t0; K.bb[a][1] = t1;
    }

    setup_rows<<<dim3((BB + 255) / 256, NA), 256>>>(ctx, y, K);
    setup_genes<<<dim3((DD + 255) / 256, NA), 256>>>(K);
    main_kernel<<<dim3((DD / 8 + 255) / 256, BB, NA), 256>>>(x, out, K);

    long long O = (long long)NA * BB * DD;
    int tail = NA * BB * 8;
    if ((long long)out_size >= O + tail)
        tail_kernel<<<(tail + 255) / 256, 256>>>(ctx, y, cont, cat, out);
}